// round 17
// baseline (speedup 1.0000x reference)
#include <cuda_runtime.h>

#define RB 131072
#define RT 6
#define RV 31
#define NJP 16            // j-pairs; j=31 zero-padded
#define XS  (RT * RV)     // 186, row stride of inp [B,T,V]
#define CTAB 64           // threads per CTA
#define BLKE 128          // 2 batch elements per thread
#define PLANE ((size_t)RB * RV)

// Inter-layer activation scratch, TIME-MAJOR [T][B][V].
__device__ float g_scratch[(size_t)RT * RB * RV];

typedef unsigned long long u64;

__device__ __forceinline__ u64 pkdup(float a) {
    u64 r;
    asm("mov.b64 %0, {%1, %1};" : "=l"(r) : "f"(a));
    return r;
}
__device__ __forceinline__ u64 pk2(float a, float b) {
    u64 r;
    asm("mov.b64 %0, {%1, %2};" : "=l"(r) : "f"(a), "f"(b));
    return r;
}
__device__ __forceinline__ void upk2(u64 v, float& x, float& y) {
    asm("mov.b64 {%0, %1}, %2;" : "=f"(x), "=f"(y) : "l"(v));
}
__device__ __forceinline__ u64 ffma2(u64 a, u64 b, u64 c) {
    u64 d;
    asm("fma.rn.f32x2 %0, %1, %2, %3;" : "=l"(d) : "l"(a), "l"(b), "l"(c));
    return d;
}
// tanh(x) = 1 - 2/(2^(2x*log2e)+1); MUFU-based, rel err ~1e-6, saturates.
__device__ __forceinline__ float tanh_fast(float x) {
    float e = exp2f(x * 2.885390081777927f);
    return 1.0f - __fdividef(2.0f, e + 1.0f);
}

// w2[k*NJP+jp] = { {Wih[j0,k],Wih[j1,k]}, {Whh[j0,k],Whh[j1,k]} }, j1==31 -> 0
__device__ __forceinline__ void fill_w(ulonglong2* w2, u64* bias2,
                                       const float* __restrict__ Wih,
                                       const float* __restrict__ Whh,
                                       const float* __restrict__ bih,
                                       const float* __restrict__ bhh,
                                       int tid)
{
    for (int i = tid; i < RV * NJP; i += CTAB) {
        int k = i / NJP, jp = i - k * NJP;
        int j0 = 2 * jp, j1 = j0 + 1;
        float a0 = Wih[j0 * RV + k];
        float a1 = (j1 < RV) ? Wih[j1 * RV + k] : 0.0f;
        float c0 = Whh[j0 * RV + k];
        float c1 = (j1 < RV) ? Whh[j1 * RV + k] : 0.0f;
        w2[i].x = pk2(a0, a1);
        w2[i].y = pk2(c0, c1);
    }
    if (tid < NJP) {
        int j0 = 2 * tid, j1 = j0 + 1;
        bias2[tid] = pk2(bih[j0] + bhh[j0],
                         (j1 < RV) ? (bih[j1] + bhh[j1]) : 0.0f);
    }
}

// One RNN layer over all T steps; 2 batch elems/thread; h in paired smem
// (hs[j*64+tid] = {h_e0, h_e1}, LDS.64 lane-stride 8B = conflict-free,
//  strictly private per thread -> NO barriers in the t-loop).
// strided=1: read inp [B,T,V]; strided=0: read g_scratch [T,B,V].
__global__ void __launch_bounds__(CTAB, 8)
rnn_layer(const float* xin, int strided,
          const float* __restrict__ h0g,
          const float* __restrict__ Wih, const float* __restrict__ Whh,
          const float* __restrict__ bih, const float* __restrict__ bhh)
{
    __shared__ ulonglong2 w2[RV * NJP];   // 7936 B
    __shared__ u64 bias2[NJP];
    __shared__ float2 hs[RV * CTAB];      // 15872 B

    const int tid = threadIdx.x;
    fill_w(w2, bias2, Wih, Whh, bih, bhh, tid);

    const size_t row0 = (size_t)blockIdx.x * BLKE + 2 * tid;
    const float* xsrc = strided ? xin : g_scratch;

    // init h from h0 (rows row0, row0+1)
    {
        const float* h0r = h0g + row0 * RV;
#pragma unroll
        for (int j = 0; j < RV; ++j)
            hs[j * CTAB + tid] = make_float2(h0r[j], h0r[j + RV]);
    }
    __syncthreads();    // publish w2/bias2 (hs slots are private)

#pragma unroll 1
    for (int t = 0; t < RT; ++t) {
        const float* xr0 = strided ? xsrc + row0 * XS + t * RV
                                   : xsrc + t * PLANE + row0 * RV;
        const float* xr1 = xr0 + (strided ? XS : RV);

        u64 acc0[NJP], acc1[NJP];
#pragma unroll
        for (int jp = 0; jp < NJP; ++jp) { acc0[jp] = bias2[jp]; acc1[jp] = bias2[jp]; }

#pragma unroll
        for (int k = 0; k < RV; ++k) {
            float2 hk = hs[k * CTAB + tid];       // LDS.64 conflict-free
            const u64 x0 = pkdup(xr0[k]);         // L1-resident after warmup
            const u64 x1 = pkdup(xr1[k]);
            const u64 h0d = pkdup(hk.x);
            const u64 h1d = pkdup(hk.y);
            const ulonglong2* wr = w2 + k * NJP;
#pragma unroll
            for (int jp = 0; jp < NJP; ++jp) {
                ulonglong2 w = wr[jp];            // broadcast LDS.128
                acc0[jp] = ffma2(w.x, x0, acc0[jp]);
                acc0[jp] = ffma2(w.y, h0d, acc0[jp]);
                acc1[jp] = ffma2(w.x, x1, acc1[jp]);
                acc1[jp] = ffma2(w.y, h1d, acc1[jp]);
            }
        }

        // tanh -> hs (private) + direct STG to scratch rows
        float* o0 = g_scratch + t * PLANE + row0 * RV;
        float* o1 = o0 + RV;
#pragma unroll
        for (int jp = 0; jp < NJP; ++jp) {
            float a0, a1, b0, b1;
            upk2(acc0[jp], a0, a1);
            upk2(acc1[jp], b0, b1);
            int j0 = 2 * jp, j1 = j0 + 1;
            float va0 = tanh_fast(a0), vb0 = tanh_fast(b0);
            hs[j0 * CTAB + tid] = make_float2(va0, vb0);
            o0[j0] = va0; o1[j0] = vb0;
            if (j1 < RV) {
                float va1 = tanh_fast(a1), vb1 = tanh_fast(b1);
                hs[j1 * CTAB + tid] = make_float2(va1, vb1);
                o0[j1] = va1; o1[j1] = vb1;
            }
        }
        // no barrier: hs private, x read-only, o write-only own rows
    }
}

// Layer 2 recurrence (no activation stores) + linear + tanh + softmax.
__global__ void __launch_bounds__(CTAB, 8)
rnn_final(const float* __restrict__ h0g,
          const float* __restrict__ Wih, const float* __restrict__ Whh,
          const float* __restrict__ bih, const float* __restrict__ bhh,
          const float* __restrict__ Wlin, const float* __restrict__ blin,
          float* __restrict__ out)
{
    __shared__ ulonglong2 w2[RV * NJP];
    __shared__ u64 bias2[NJP];
    __shared__ u64 wl[RV * NJP];          // {Wlin[j0,k], Wlin[j1,k]}
    __shared__ u64 bl[NJP];
    __shared__ float2 hs[RV * CTAB];

    const int tid = threadIdx.x;
    fill_w(w2, bias2, Wih, Whh, bih, bhh, tid);
    for (int i = tid; i < RV * NJP; i += CTAB) {
        int k = i / NJP, jp = i - k * NJP;
        int j0 = 2 * jp, j1 = j0 + 1;
        wl[i] = pk2(Wlin[j0 * RV + k], (j1 < RV) ? Wlin[j1 * RV + k] : 0.0f);
    }
    if (tid < NJP) {
        int j0 = 2 * tid, j1 = j0 + 1;
        bl[tid] = pk2(blin[j0], (j1 < RV) ? blin[j1] : 0.0f);
    }

    const size_t row0 = (size_t)blockIdx.x * BLKE + 2 * tid;
    {
        const float* h0r = h0g + row0 * RV;
#pragma unroll
        for (int j = 0; j < RV; ++j)
            hs[j * CTAB + tid] = make_float2(h0r[j], h0r[j + RV]);
    }
    __syncthreads();

#pragma unroll 1
    for (int t = 0; t < RT; ++t) {
        const float* xr0 = g_scratch + t * PLANE + row0 * RV;
        const float* xr1 = xr0 + RV;

        u64 acc0[NJP], acc1[NJP];
#pragma unroll
        for (int jp = 0; jp < NJP; ++jp) { acc0[jp] = bias2[jp]; acc1[jp] = bias2[jp]; }

#pragma unroll
        for (int k = 0; k < RV; ++k) {
            float2 hk = hs[k * CTAB + tid];
            const u64 x0 = pkdup(xr0[k]);
            const u64 x1 = pkdup(xr1[k]);
            const u64 h0d = pkdup(hk.x);
            const u64 h1d = pkdup(hk.y);
            const ulonglong2* wr = w2 + k * NJP;
#pragma unroll
            for (int jp = 0; jp < NJP; ++jp) {
                ulonglong2 w = wr[jp];
                acc0[jp] = ffma2(w.x, x0, acc0[jp]);
                acc0[jp] = ffma2(w.y, h0d, acc0[jp]);
                acc1[jp] = ffma2(w.x, x1, acc1[jp]);
                acc1[jp] = ffma2(w.y, h1d, acc1[jp]);
            }
        }
#pragma unroll
        for (int jp = 0; jp < NJP; ++jp) {
            float a0, a1, b0, b1;
            upk2(acc0[jp], a0, a1);
            upk2(acc1[jp], b0, b1);
            int j0 = 2 * jp, j1 = j0 + 1;
            hs[j0 * CTAB + tid] = make_float2(tanh_fast(a0), tanh_fast(b0));
            if (j1 < RV)
                hs[j1 * CTAB + tid] = make_float2(tanh_fast(a1), tanh_fast(b1));
        }
    }

    // linear from hs
    u64 l0[NJP], l1[NJP];
#pragma unroll
    for (int jp = 0; jp < NJP; ++jp) { l0[jp] = bl[jp]; l1[jp] = bl[jp]; }
#pragma unroll
    for (int k = 0; k < RV; ++k) {
        float2 hk = hs[k * CTAB + tid];
        const u64 h0d = pkdup(hk.x);
        const u64 h1d = pkdup(hk.y);
        const u64* wr = wl + k * NJP;
#pragma unroll
        for (int jp = 0; jp < NJP; ++jp) {
            u64 w = wr[jp];
            l0[jp] = ffma2(w, h0d, l0[jp]);
            l1[jp] = ffma2(w, h1d, l1[jp]);
        }
    }

    float ya[2 * NJP], yb[2 * NJP];
#pragma unroll
    for (int jp = 0; jp < NJP; ++jp) {
        float a0, a1, b0, b1;
        upk2(l0[jp], a0, a1);
        upk2(l1[jp], b0, b1);
        ya[2 * jp] = tanh_fast(a0);
        yb[2 * jp] = tanh_fast(b0);
        ya[2 * jp + 1] = (2 * jp + 1 < RV) ? tanh_fast(a1) : -1e30f;
        yb[2 * jp + 1] = (2 * jp + 1 < RV) ? tanh_fast(b1) : -1e30f;
    }

    // softmax per element + direct stores (own rows)
    float* oa = out + row0 * RV;
    float* ob = oa + RV;
    {
        float m = ya[0];
#pragma unroll
        for (int j = 1; j < RV; ++j) m = fmaxf(m, ya[j]);
        float s = 0.0f;
#pragma unroll
        for (int j = 0; j < RV; ++j) { ya[j] = __expf(ya[j] - m); s += ya[j]; }
        float inv = __fdividef(1.0f, s);
#pragma unroll
        for (int j = 0; j < RV; ++j) oa[j] = ya[j] * inv;
    }
    {
        float m = yb[0];
#pragma unroll
        for (int j = 1; j < RV; ++j) m = fmaxf(m, yb[j]);
        float s = 0.0f;
#pragma unroll
        for (int j = 0; j < RV; ++j) { yb[j] = __expf(yb[j] - m); s += yb[j]; }
        float inv = __fdividef(1.0f, s);
#pragma unroll
        for (int j = 0; j < RV; ++j) ob[j] = yb[j] * inv;
    }
}

extern "C" void kernel_launch(void* const* d_in, const int* in_sizes, int n_in,
                              void* d_out, int out_size)
{
    const float* inp  = (const float*)d_in[0];  // [B,T,V]
    const float* h0   = (const float*)d_in[1];  // [L,B,V]
    const float* Wih  = (const float*)d_in[2];  // [L,V,V]
    const float* Whh  = (const float*)d_in[3];  // [L,V,V]
    const float* bih  = (const float*)d_in[4];  // [L,V]
    const float* bhh  = (const float*)d_in[5];  // [L,V]
    const float* Wlin = (const float*)d_in[6];  // [V,V]
    const float* blin = (const float*)d_in[7];  // [V]
    float* out = (float*)d_out;                 // [B,V]

    (void)in_sizes; (void)n_in; (void)out_size;

    const dim3 grid(RB / BLKE), block(CTAB);    // 1024 x 64

    // layer 0: inp [B,T,V] (strided) -> scratch [T,B,V]
    rnn_layer<<<grid, block>>>(inp, 1, h0, Wih, Whh, bih, bhh);
    // layer 1: scratch -> scratch (own rows, in-place per thread)
    rnn_layer<<<grid, block>>>(nullptr, 0, h0 + (size_t)RB * RV,
                               Wih + RV * RV, Whh + RV * RV,
                               bih + RV, bhh + RV);
    // layer 2 + linear + tanh + softmax
    rnn_final<<<grid, block>>>(h0 + 2 * (size_t)RB * RV,
                               Wih + 2 * RV * RV, Whh + 2 * RV * RV,
                               bih + 2 * RV, bhh + 2 * RV,
                               Wlin, blin, out);
}